// round 3
// baseline (speedup 1.0000x reference)
#include <cuda_runtime.h>
#include <math.h>

// ---------------------------------------------------------------------------
// GraphConvolution (hyperbolic GCN layer), fp32 — fused pipeline:
//   1. k_gemm_fused: mx = x@W (SIMT 64x64 tile), per-row ||x|| during load,
//      acc staged to smem, warp-per-row hyperbolic epilogue
//      (mobius_matvec scale + mobius_add(hb) + logmap0), zero accum rows.
//   2. k_spmm:  accum[row] += vals * tmp[col]   (float4 vector RED)
//   3. k_final: out = proj(expmap0(accum, c), c)
// ---------------------------------------------------------------------------

#define MAXN  50432
#define FOUT  64
#define MIN_NORM 1e-15f
#define BALL_EPS 4e-3f

__device__ float g_tmp[MAXN * FOUT];
__device__ float g_accum[MAXN * FOUT];

__device__ __forceinline__ float warp_sum(float v) {
    #pragma unroll
    for (int o = 16; o > 0; o >>= 1) v += __shfl_xor_sync(0xffffffffu, v, o);
    return v;
}

// fast tanh via __expf; arg clamped to avoid inf/inf
__device__ __forceinline__ float tanh_fast(float x) {
    x = fminf(x, 15.0f);                   // x >= 0 in all our uses
    float e = __expf(2.0f * x);
    return (e - 1.0f) / (e + 1.0f);
}
// fast artanh with reference clamping
__device__ __forceinline__ float artanh_fast(float v) {
    v = fminf(fmaxf(v, -1.0f + 1e-7f), 1.0f - 1e-7f);
    return 0.5f * __logf((1.0f + v) / (1.0f - v));
}

// --- 1. fused GEMM + row-wise epilogues --------------------------------------
#define BM 64
#define BN 64
#define BK 32
#define POOL_FLOATS (BK * (BM + 4) + BK * BN)   // 4224 >= 64*64

__global__ void __launch_bounds__(256, 3)
k_gemm_fused(const float* __restrict__ X, const float* __restrict__ W,
             const float* __restrict__ bias, const float* __restrict__ cp,
             int N, int IN) {
    __shared__ float pool[POOL_FLOATS];
    __shared__ float s_xn[BM];
    __shared__ float s_hb[FOUT];
    __shared__ float s_y2;

    float* As = pool;                         // [BK][BM+4]
    float* Bs = pool + BK * (BM + 4);         // [BK][BN]

    int tid  = threadIdx.x;             // 256 threads
    int lane = tid & 31;
    int wrp  = tid >> 5;                // 0..7
    int block_row = blockIdx.x * BM;
    int tx = tid & 15;                  // 16 col groups (4 cols each)
    int ty = tid >> 4;                  // 16 row groups (4 rows each)

    float c  = cp[0];
    float sc = sqrtf(c);

    // warp 0: hyperbolic bias  hb = proj(expmap0(bias, c), c) and ||hb||^2
    if (wrp == 0) {
        float u0 = bias[lane], u1 = bias[lane + 32];
        float un = fmaxf(sqrtf(warp_sum(u0 * u0 + u1 * u1)), MIN_NORM);
        float scale = tanh_fast(sc * un) / (sc * un);
        float p0 = scale * u0, p1 = scale * u1;
        float pn = fmaxf(sqrtf(warp_sum(p0 * p0 + p1 * p1)), MIN_NORM);
        float maxn = (1.0f - BALL_EPS) / sc;
        float f = (pn > maxn) ? (maxn / pn) : 1.0f;
        s_hb[lane]      = p0 * f;
        s_hb[lane + 32] = p1 * f;
        if (lane == 0) {
            float hn = fminf(pn, maxn);
            s_y2 = hn * hn;
        }
    }

    float acc[4][4] = {};
    float xsum[8] = {};   // partial ||x||^2 ; thread tid covers rows wrp+8i

    for (int k0 = 0; k0 < IN; k0 += BK) {
        #pragma unroll
        for (int i = 0; i < (BM * BK) / 256; i++) {      // 8 iters
            int idx = tid + i * 256;
            int r  = idx >> 5;          // = wrp + 8*i
            int cc = idx & 31;
            int gr = block_row + r;
            float v = (gr < N) ? X[(size_t)gr * IN + k0 + cc] : 0.f;
            As[cc * (BM + 4) + r] = v;
            xsum[i] += v * v;
        }
        #pragma unroll
        for (int i = 0; i < (BK * BN) / 256; i++) {
            int idx = tid + i * 256;
            int r  = idx >> 6;
            int cc = idx & 63;
            Bs[r * BN + cc] = W[(size_t)(k0 + r) * BN + cc];
        }
        __syncthreads();
        #pragma unroll
        for (int k = 0; k < BK; k++) {
            float a[4], b[4];
            #pragma unroll
            for (int i = 0; i < 4; i++) a[i] = As[k * (BM + 4) + ty * 4 + i];
            #pragma unroll
            for (int j = 0; j < 4; j++) b[j] = Bs[k * BN + tx * 4 + j];
            #pragma unroll
            for (int i = 0; i < 4; i++)
                #pragma unroll
                for (int j = 0; j < 4; j++)
                    acc[i][j] += a[i] * b[j];
        }
        __syncthreads();
    }

    // per-row ||x||: warp w owns rows {w + 8i}
    #pragma unroll
    for (int i = 0; i < 8; i++) {
        float s = warp_sum(xsum[i]);
        if (lane == 0) s_xn[wrp + 8 * i] = fmaxf(sqrtf(s), MIN_NORM);
    }

    // stage acc tile into smem (reuses As/Bs space; last sync above protects it)
    #pragma unroll
    for (int i = 0; i < 4; i++) {
        float4 v = make_float4(acc[i][0], acc[i][1], acc[i][2], acc[i][3]);
        *reinterpret_cast<float4*>(pool + (ty * 4 + i) * BN + tx * 4) = v;
    }

    // zero accumulator rows for this block (overlaps the sync)
    {
        float4 z = make_float4(0.f, 0.f, 0.f, 0.f);
        float4* ab = reinterpret_cast<float4*>(g_accum + (size_t)block_row * FOUT);
        int lim4 = ((N - block_row) < BM ? (N - block_row) : BM) * FOUT / 4;
        #pragma unroll
        for (int i = 0; i < (BM * FOUT / 4) / 256; i++) {
            int idx = tid + i * 256;
            if (idx < lim4) ab[idx] = z;
        }
    }
    __syncthreads();

    // epilogue: warp-per-row from smem; each warp handles 8 rows
    float y2 = s_y2;
    float h0 = s_hb[lane], h1 = s_hb[lane + 32];

    for (int i = 0; i < 8; i++) {
        int r = wrp * 8 + i;                 // local row
        int row = block_row + r;
        if (row >= N) break;                 // warp-uniform

        float mx0 = pool[r * BN + lane];
        float mx1 = pool[r * BN + lane + 32];

        float smx = warp_sum(mx0 * mx0 + mx1 * mx1);   // ||mx||^2
        float sxh = warp_sum(mx0 * h0 + mx1 * h1);     // mx . hb

        float x_n = s_xn[r];
        float mxn = fmaxf(sqrtf(smx), MIN_NORM);
        float at  = artanh_fast(sc * x_n);
        float scl = tanh_fast(mxn / x_n * at) / (mxn * sc);
        if (smx == 0.0f) scl = 0.0f;

        float x2 = scl * scl * smx;          // ||r||^2
        float xy = scl * sxh;                // r . hb

        float A = 1.0f + 2.0f * c * xy + c * y2;
        float B = 1.0f - c * x2;
        float den = fmaxf(1.0f + 2.0f * c * xy + c * c * x2 * y2, MIN_NORM);
        float inv_den = 1.0f / den;

        float a0 = (A * (scl * mx0) + B * h0) * inv_den;
        float a1 = (A * (scl * mx1) + B * h1) * inv_den;

        float pn = fmaxf(sqrtf(warp_sum(a0 * a0 + a1 * a1)), MIN_NORM);
        float t = artanh_fast(sc * pn) / (sc * pn);

        g_tmp[(size_t)row * FOUT + lane]      = t * a0;
        g_tmp[(size_t)row * FOUT + lane + 32] = t * a1;
    }
}

// --- 2. SpMM: accum[row[e]] += vals[e] * tmp[col[e]] --------------------------
__global__ void k_spmm(const float* __restrict__ vals, const int* __restrict__ row,
                       const int* __restrict__ col, int E) {
    int g = blockIdx.x * blockDim.x + threadIdx.x;
    int e = g >> 4;
    int lane = g & 15;
    if (e >= E) return;
    int cc = __ldg(col + e);
    int rr = __ldg(row + e);
    float v = __ldg(vals + e);
    float4 t = *reinterpret_cast<const float4*>(g_tmp + (size_t)cc * FOUT + lane * 4);
    float4 a = make_float4(t.x * v, t.y * v, t.z * v, t.w * v);
    atomicAdd(reinterpret_cast<float4*>(g_accum + (size_t)rr * FOUT) + lane, a);
}

// --- 3. final: out = proj(expmap0(accum)) ------------------------------------
__global__ void k_final(const float* __restrict__ cp, float* __restrict__ out, int N) {
    int warp = (blockIdx.x * blockDim.x + threadIdx.x) >> 5;
    int lane = threadIdx.x & 31;
    if (warp >= N) return;
    float c = cp[0];
    float sc = sqrtf(c);
    size_t base = (size_t)warp * FOUT;
    float u0 = g_accum[base + lane];
    float u1 = g_accum[base + lane + 32];
    float un = fmaxf(sqrtf(warp_sum(u0 * u0 + u1 * u1)), MIN_NORM);
    float scale = tanh_fast(sc * un) / (sc * un);
    float p0 = scale * u0, p1 = scale * u1;
    float pn = fmaxf(sqrtf(warp_sum(p0 * p0 + p1 * p1)), MIN_NORM);
    float maxn = (1.0f - BALL_EPS) / sc;
    float f = (pn > maxn) ? (maxn / pn) : 1.0f;
    out[base + lane]      = p0 * f;
    out[base + lane + 32] = p1 * f;
}

// ---------------------------------------------------------------------------

extern "C" void kernel_launch(void* const* d_in, const int* in_sizes, int n_in,
                              void* d_out, int out_size) {
    const float* x    = (const float*)d_in[0];
    const float* w    = (const float*)d_in[1];
    const float* bias = (const float*)d_in[2];
    const float* vals = (const float*)d_in[3];
    const float* c    = (const float*)d_in[4];
    const int*   row  = (const int*)d_in[5];
    const int*   col  = (const int*)d_in[6];
    float* out = (float*)d_out;

    int OUT = in_sizes[2];               // 64
    int IN  = in_sizes[1] / OUT;         // 256
    int N   = in_sizes[0] / IN;          // 50000
    int E   = in_sizes[3];               // 800000
    (void)OUT; (void)n_in; (void)out_size;

    // 1. fused GEMM + epilogues (+ accumulator zeroing)
    k_gemm_fused<<<(N + BM - 1) / BM, 256>>>(x, w, bias, c, N, IN);

    // 2. SpMM scatter-add
    long long tot = (long long)E * 16;
    k_spmm<<<(int)((tot + 255) / 256), 256>>>(vals, row, col, E);

    // 3. final expmap0 + proj
    int rowBlocks = (N + 7) / 8;
    k_final<<<rowBlocks, 256>>>(c, out, N);
}